// round 12
// baseline (speedup 1.0000x reference)
#include <cuda_runtime.h>
#include <cstdint>
#include <cstddef>

// Problem constants
#define D   384
#define S   512
#define NB  8
#define NPOS (NB*S)          // 4096
#define DD  (D*D)            // 147456
#define MC  8                // positions per pass (cnt<=8 for this seed; fallback loops)

// k2 pipeline geometry
#define T2         384
#define STAGES     6
#define SLICE_ROWS 8
#define SLICE_F    (SLICE_ROWS*D)   // 3072 floats = 12KB per slice
#define NSLICES    (D/SLICE_ROWS)   // 48 slices per o-tile
#define K2_SMEM    (STAGES*SLICE_F*4 + MC*D*8 + MC*12*4)   // 73728+24576+384 = 98688B

// ---------------- scratch (device globals; no allocation allowed) ----------
__device__ int   g_count;
__device__ int   g_list[NPOS];
__device__ float g_toff[D];
__device__ float g_base[D];
__device__ __align__(16) float g_tok[NPOS * D];
__device__ __align__(16) float g_dep[NPOS * D];
__device__ __align__(16) float g_u  [NPOS * D];

// ---------------- packed f32x2 + async-copy helpers (sm_103a) ---------------
__device__ __forceinline__ unsigned long long fma2(unsigned long long a,
                                                   unsigned long long b,
                                                   unsigned long long c) {
    unsigned long long r;
    asm("fma.rn.f32x2 %0, %1, %2, %3;" : "=l"(r) : "l"(a), "l"(b), "l"(c));
    return r;
}
__device__ __forceinline__ unsigned long long pack2(float x, float y) {
    unsigned long long r;
    asm("mov.b64 %0, {%1, %2};" : "=l"(r) : "f"(x), "f"(y));
    return r;
}
__device__ __forceinline__ float hadd2(unsigned long long a) {
    float x, y;
    asm("mov.b64 {%0, %1}, %2;" : "=f"(x), "=f"(y) : "l"(a));
    return x + y;
}
__device__ __forceinline__ void cp16(uint32_t smem_dst, const void* gsrc) {
    asm volatile("cp.async.cg.shared.global [%0], [%1], 16;"
                 :: "r"(smem_dst), "l"(gsrc));
}

// ---------------- K0: scalars + counter reset -------------------------------
__global__ void k0_scalars(const float* __restrict__ Wr,
                           const float* __restrict__ bc,
                           const float* __restrict__ br) {
    __shared__ float red[512];
    int t = threadIdx.x;                 // 512 threads
    red[t] = Wr[t];
    __syncthreads();
    for (int ofs = 256; ofs > 0; ofs >>= 1) {
        if (t < ofs) red[t] += red[t + ofs];
        __syncthreads();
    }
    float sumw = red[0];
    if (t < D) {
        float to = tanhf(bc[t]);
        g_toff[t] = to;
        g_base[t] = to * sumw + br[0];
    }
    if (t == 0) g_count = 0;
}

// ---------------- K1: output init + active list + fused gather/prep ---------
// out[b,s1,:] = base if dep_heads[b,s1]==0 else 0.
// Position r=(b,s2) active iff dep_heads[b, dep_heads[b,s2]] == 0.
__global__ void k1_init(const int* __restrict__ heads,
                        const int* __restrict__ tokens,
                        const float* __restrict__ table,
                        float* __restrict__ out) {
    int r = blockIdx.x;                  // r = b*S + s1  (also acts as s2)
    int t = threadIdx.x;                 // 384 threads
    __shared__ int s_idx;
    bool m = (heads[r] == 0);
    out[(size_t)r * D + t] = m ? g_base[t] : 0.0f;
    if (t == 0) {
        int b0 = r & ~(S - 1);           // b*S
        int idx = -1;
        if (heads[b0 + heads[r]] == 0) {
            idx = atomicAdd(&g_count, 1);
            g_list[idx] = r;
        }
        s_idx = idx;
    }
    __syncthreads();
    int idx = s_idx;
    if (idx >= 0) {
        int tok_id = tokens[r];
        float v = table[(size_t)tok_id * D + t];
        g_tok[idx * D + t] = v;
        g_dep[idx * D + t] = tanhf(v);
        g_u  [idx * D + t] = 0.0f;
    }
}

// ---------------- K2: cp.async-pipelined bilinear ---------------------------
// u[i][o] = sum_{d,e} tok_i[d] * Wc[o,d,e] * dep_i[e]
// One block per o; Wc[o] (576KB) streamed once through a 6-stage 12KB-slice
// smem ring. 384 threads = 4 d-subrow groups (2 rows/slice each) x 96 e-quads.
__device__ __forceinline__ void k2_issue_slice(const float* __restrict__ wc_o,
                                               uint32_t s_wbase, int s, int t) {
    uint32_t dst = s_wbase + (uint32_t)(s % STAGES) * (SLICE_F * 4) + (uint32_t)t * 16;
    const float* src = wc_o + (size_t)s * SLICE_F + t * 4;
    cp16(dst,            src);
    cp16(dst + 384 * 16, src + 1536);
}

__global__ void __launch_bounds__(T2) k2_bilinear(const float* __restrict__ Wc) {
    extern __shared__ unsigned char s_raw[];
    float* wstage = (float*)s_raw;                                   // 72KB ring
    unsigned long long* tok2 = (unsigned long long*)(wstage + STAGES * SLICE_F);
    float* red = (float*)(tok2 + MC * D);

    const int t  = threadIdx.x;
    const int q  = t % 96;               // e-quad
    const int p  = t / 96;               // d-subrow group (2 rows per slice)
    const int e0 = 4 * q;
    const int o  = blockIdx.x;
    const int cnt = g_count;
    const float* wc_o = Wc + (size_t)o * DD;
    const uint32_t s_wbase = (uint32_t)__cvta_generic_to_shared(wstage);

    for (int c0 = 0; c0 < cnt; c0 += MC) {
        // stage tok packed (v,v) for all 384 d, MC positions
        for (int idx = t; idx < MC * D; idx += T2) {
            int i = idx / D, dl = idx - i * D;
            float v = (c0 + i < cnt) ? g_tok[(c0 + i) * D + dl] : 0.0f;
            tok2[idx] = pack2(v, v);
        }
        // dep quads in registers (fixed per thread for whole tile)
        unsigned long long dlo[MC], dhi[MC];
#pragma unroll
        for (int i = 0; i < MC; i++) {
            float4 dv = make_float4(0.f, 0.f, 0.f, 0.f);
            if (c0 + i < cnt)
                dv = *reinterpret_cast<const float4*>(&g_dep[(c0 + i) * D + e0]);
            dlo[i] = pack2(dv.x, dv.y);
            dhi[i] = pack2(dv.z, dv.w);
        }
        unsigned long long s2[MC];
#pragma unroll
        for (int i = 0; i < MC; i++) s2[i] = 0ULL;
        __syncthreads();                 // tok2 ready (also fences red reuse)

        // pipeline prologue: STAGES-1 slices in flight
#pragma unroll
        for (int s = 0; s < STAGES - 1; s++) {
            k2_issue_slice(wc_o, s_wbase, s, t);
            asm volatile("cp.async.commit_group;");
        }

        for (int s = 0; s < NSLICES; s++) {
            asm volatile("cp.async.wait_group %0;" :: "n"(STAGES - 2));
            __syncthreads();             // slice s landed for everyone
            const float* wbuf = wstage + (s % STAGES) * SLICE_F;
#pragma unroll
            for (int j = 0; j < 2; j++) {
                int drow = p * 2 + j;
                float4 wv = *reinterpret_cast<const float4*>(&wbuf[drow * D + e0]);
                unsigned long long wlo = pack2(wv.x, wv.y);
                unsigned long long whi = pack2(wv.z, wv.w);
                const unsigned long long* tkp = tok2 + (s * SLICE_ROWS + drow);
#pragma unroll
                for (int i = 0; i < MC; i++) {
                    unsigned long long q2 = fma2(wlo, dlo[i], fma2(whi, dhi[i], 0ULL));
                    s2[i] = fma2(tkp[i * D], q2, s2[i]);
                }
            }
            __syncthreads();             // done reading buffer before refill
            int sn = s + STAGES - 1;
            if (sn < NSLICES) k2_issue_slice(wc_o, s_wbase, sn, t);
            asm volatile("cp.async.commit_group;");   // empty groups keep count uniform
        }

        // reduce over 384 threads per position (once per tile)
        const int lane = t & 31, wid = t >> 5;   // 12 warps
#pragma unroll
        for (int i = 0; i < MC; i++) {
            float v = hadd2(s2[i]);
            for (int ofs = 16; ofs; ofs >>= 1)
                v += __shfl_down_sync(0xffffffffu, v, ofs);
            if (lane == 0) red[i * 12 + wid] = v;
        }
        __syncthreads();
        if (t < MC && c0 + t < cnt) {
            float acc = 0.0f;
#pragma unroll
            for (int w = 0; w < 12; w++) acc += red[t * 12 + w];
            atomicAdd(&g_u[(c0 + t) * D + o], acc);
        }
    }
}

// ---------------- K3: epilogue + scatter ------------------------------------
__global__ void k3_scatter(const int* __restrict__ heads,
                           const float* __restrict__ Wr,
                           const float* __restrict__ bc,
                           float* __restrict__ out) {
    int t = threadIdx.x;                 // 384 threads
    int cnt = g_count;
    for (int i = blockIdx.x; i < cnt; i += gridDim.x) {
        int r = g_list[i];
        int h = heads[r];
        float w = Wr[r & (S - 1)];
        int row = (r & ~(S - 1)) + h;
        float u = g_u[i * D + t];
        float ton = tanhf(u + bc[t]);
        float c = (ton - g_toff[t]) * w;
        atomicAdd(&out[(size_t)row * D + t], c);
    }
}

// ---------------- launch -----------------------------------------------------
extern "C" void kernel_launch(void* const* d_in, const int* in_sizes, int n_in,
                              void* d_out, int out_size) {
    const int*   tokens = (const int*)  d_in[0];
    // d_in[1] = dep_types: computed-but-discarded in the reference; unused.
    const int*   heads  = (const int*)  d_in[2];
    const float* table  = (const float*)d_in[3];
    const float* Wc     = (const float*)d_in[4];
    const float* bc     = (const float*)d_in[5];
    const float* Wr     = (const float*)d_in[6];
    const float* br     = (const float*)d_in[7];
    float* out = (float*)d_out;

    // idempotent, not a stream op; legal under graph capture
    cudaFuncSetAttribute(k2_bilinear,
                         cudaFuncAttributeMaxDynamicSharedMemorySize, K2_SMEM);

    k0_scalars<<<1, 512>>>(Wr, bc, br);
    k1_init   <<<NPOS, D>>>(heads, tokens, table, out);
    k2_bilinear<<<D, T2, K2_SMEM>>>(Wc);     // one block per o-channel
    k3_scatter<<<64, D>>>(heads, Wr, bc, out);
}